// round 5
// baseline (speedup 1.0000x reference)
#include <cuda_runtime.h>
#include <math.h>

// ---- problem constants -----------------------------------------------------
constexpr int NN   = 62;    // nodes per graph
constexpr int BB   = 512;   // graphs
constexpr int FIN  = 128;   // input features
constexpr int HH   = 64;    // hidden
constexpr int CC   = 3;     // classes

// padded smem row strides (floats)
constexpr int XS  = 132;    // X rows: 528B, 16B-aligned walk
constexpr int A2S = 65;     // A2 rows: (row+k)%32 -> conflict-free scalar LDS
constexpr int MS  = 68;     // M rows: 272B, 16B aligned

// region sizes in floats, each rounded up to a multiple of 4 (16B) so every
// region START stays 16B-aligned (round-2 bug: 62*65=4030 floats broke sM).
constexpr int SZ_X   = NN * XS;                    // 8184  (mult of 4)
constexpr int SZ_W1  = HH * FIN;                   // 8192  (mult of 4)
constexpr int SZ_A2  = ((NN * A2S + 3) / 4) * 4;   // 4030 -> 4032
constexpr int SZ_M   = NN * MS;                    // 4216  (mult of 4)
constexpr int SZ_B1  = HH;                         // 64
constexpr int SZ_PL  = 128;
constexpr int SZ_PD  = HH;
constexpr int SMEM_FLOATS = SZ_X + SZ_W1 + SZ_A2 + SZ_M + SZ_B1 + SZ_PL + SZ_PD;

__device__ float g_A2[NN * NN];

// ---- prep: build normalized A = D^-1/2 Wsym D^-1/2, then A2 = A@A ----------
__global__ void prep_kernel(const float* __restrict__ tril) {
    __shared__ float A[NN][64];
    __shared__ float dinv[NN];
    int tid = threadIdx.x;

    // Wsym from lower-tri params: element (i,j) at idx(max,min) = a*(a+1)/2 + b
    for (int idx = tid; idx < NN * NN; idx += blockDim.x) {
        int i = idx / NN, j = idx - i * NN;
        int a = i > j ? i : j;
        int b = i > j ? j : i;
        A[i][j] = tril[a * (a + 1) / 2 + b];
    }
    __syncthreads();

    if (tid < NN) {
        float s = 0.f;
        for (int j = 0; j < NN; ++j) s += fabsf(A[tid][j]);
        dinv[tid] = s > 0.f ? rsqrtf(s) : 0.f;
    }
    __syncthreads();

    for (int idx = tid; idx < NN * NN; idx += blockDim.x) {
        int i = idx / NN, j = idx - i * NN;
        A[i][j] *= dinv[i] * dinv[j];
    }
    __syncthreads();

    for (int idx = tid; idx < NN * NN; idx += blockDim.x) {
        int i = idx / NN, j = idx - i * NN;
        float s = 0.f;
        #pragma unroll 2
        for (int k = 0; k < NN; ++k) s += A[i][k] * A[k][j];
        g_A2[idx] = s;
    }
}

// ---- main: per-graph fused  M = X W1^T;  Y = A2 M;  relu+b1; pool; head ----
__global__ __launch_bounds__(256, 2)
void graph_kernel(const float* __restrict__ x,
                  const float* __restrict__ W1,
                  const float* __restrict__ b1,
                  const float* __restrict__ W2,
                  const float* __restrict__ b2,
                  float* __restrict__ out) {
    extern __shared__ float sm[];
    float* sX      = sm;                     // SZ_X
    float* sW1     = sX  + SZ_X;             // SZ_W1
    float* sA2     = sW1 + SZ_W1;            // SZ_A2 (padded to 16B multiple)
    float* sM      = sA2 + SZ_A2;            // SZ_M  -> 16B aligned now
    float* sB1     = sM  + SZ_M;             // HH
    float* sPool   = sB1 + SZ_B1;            // 8*16
    float* sPooled = sPool + SZ_PL;          // HH

    const int tid  = threadIdx.x;
    const int g    = blockIdx.x;
    const int w    = tid >> 5;
    const int lane = tid & 31;
    const int row  = (w >> 2) * 32 + lane;       // node row 0..63 (valid < 62)
    const int hBase = (w & 3) * 16;              // this warp's 16 hidden cols

    // ---- stage 0: stage inputs to smem ----
    const float4* xg = (const float4*)(x + (size_t)g * NN * FIN);
    for (int t = tid; t < NN * (FIN / 4); t += 256) {
        int i = t >> 5;            // t / 32  (FIN/4 == 32)
        int f4 = t & 31;
        *(float4*)(sX + i * XS + f4 * 4) = xg[t];
    }
    const float4* w1g = (const float4*)W1;
    for (int t = tid; t < HH * (FIN / 4); t += 256)
        ((float4*)sW1)[t] = w1g[t];
    for (int t = tid; t < NN * NN; t += 256) {
        int i = t / NN, j = t - i * NN;
        sA2[i * A2S + j] = g_A2[t];
    }
    if (tid < HH) sB1[tid] = b1[tid];
    __syncthreads();

    // ---- stage 1: M[row][hBase..+15] = X[row] . W1[h]  (W1 warp-broadcast) ----
    if (row < NN) {
        float acc[16];
        #pragma unroll
        for (int c = 0; c < 16; ++c) acc[c] = 0.f;
        const float4* xr = (const float4*)(sX + row * XS);
        #pragma unroll 2
        for (int f4 = 0; f4 < FIN / 4; ++f4) {
            float4 xv = xr[f4];
            #pragma unroll
            for (int c = 0; c < 16; ++c) {
                float4 wv = *(const float4*)(sW1 + (hBase + c) * FIN + f4 * 4);
                acc[c] += xv.x * wv.x;
                acc[c] += xv.y * wv.y;
                acc[c] += xv.z * wv.z;
                acc[c] += xv.w * wv.w;
            }
        }
        #pragma unroll
        for (int c = 0; c < 16; c += 4)
            *(float4*)(sM + row * MS + hBase + c) =
                make_float4(acc[c], acc[c + 1], acc[c + 2], acc[c + 3]);
    }
    __syncthreads();

    // ---- stage 2: Y = A2 @ M ; relu(Y + b1); warp-reduce pool over rows ----
    float part[16];
    #pragma unroll
    for (int c = 0; c < 16; ++c) part[c] = 0.f;

    if (row < NN) {
        float acc[16];
        #pragma unroll
        for (int c = 0; c < 16; ++c) acc[c] = 0.f;
        const float* ar = sA2 + row * A2S;
        #pragma unroll 2
        for (int k = 0; k < NN; ++k) {
            float a = ar[k];                               // conflict-free (pad 65)
            const float4* mr = (const float4*)(sM + k * MS + hBase);  // broadcast
            #pragma unroll
            for (int c4 = 0; c4 < 4; ++c4) {
                float4 mv = mr[c4];
                acc[c4 * 4 + 0] += a * mv.x;
                acc[c4 * 4 + 1] += a * mv.y;
                acc[c4 * 4 + 2] += a * mv.z;
                acc[c4 * 4 + 3] += a * mv.w;
            }
        }
        #pragma unroll
        for (int c = 0; c < 16; ++c)
            part[c] = fmaxf(acc[c] + sB1[hBase + c], 0.f);
    }
    // reduce over 32 row-lanes (invalid rows contribute 0)
    #pragma unroll
    for (int c = 0; c < 16; ++c) {
        #pragma unroll
        for (int off = 16; off; off >>= 1)
            part[c] += __shfl_xor_sync(0xffffffffu, part[c], off);
    }
    if (lane == 0) {
        #pragma unroll
        for (int c = 0; c < 16; ++c) sPool[w * 16 + c] = part[c];
    }
    __syncthreads();

    // ---- stage 3: combine row-halves -> latent out; tiny head + log_softmax ----
    if (tid < HH) {
        float p = sPool[tid] + sPool[64 + tid];   // h == tid
        sPooled[tid] = p;
        out[(size_t)g * HH + tid] = p;            // latent_v
    }
    __syncthreads();

    if (tid < 32) {
        float p0 = sPooled[tid], p1 = sPooled[tid + 32];
        float l[CC];
        #pragma unroll
        for (int cc = 0; cc < CC; ++cc) {
            l[cc] = p0 * W2[cc * HH + tid] + p1 * W2[cc * HH + tid + 32];
            #pragma unroll
            for (int off = 16; off; off >>= 1)
                l[cc] += __shfl_xor_sync(0xffffffffu, l[cc], off);
        }
        if (tid == 0) {
            float l0 = l[0] + b2[0];
            float l1 = l[1] + b2[1];
            float l2 = l[2] + b2[2];
            float m  = fmaxf(l0, fmaxf(l1, l2));
            float lse = m + logf(expf(l0 - m) + expf(l1 - m) + expf(l2 - m));
            float* lp = out + (size_t)BB * HH + (size_t)g * CC;
            lp[0] = l0 - lse;
            lp[1] = l1 - lse;
            lp[2] = l2 - lse;
        }
    }
}

// ---- launch -----------------------------------------------------------------
extern "C" void kernel_launch(void* const* d_in, const int* in_sizes, int n_in,
                              void* d_out, int out_size) {
    (void)in_sizes; (void)n_in; (void)out_size;
    const float* x    = (const float*)d_in[0];
    const float* tril = (const float*)d_in[1];
    const float* W1   = (const float*)d_in[2];
    const float* b1   = (const float*)d_in[3];
    const float* W2   = (const float*)d_in[4];
    const float* b2   = (const float*)d_in[5];
    float* out = (float*)d_out;

    const int smem_bytes = SMEM_FLOATS * (int)sizeof(float);
    cudaFuncSetAttribute(graph_kernel,
                         cudaFuncAttributeMaxDynamicSharedMemorySize, smem_bytes);

    prep_kernel<<<1, 256>>>(tril);
    graph_kernel<<<BB, 256, smem_bytes>>>(x, W1, b1, W2, b2, out);
}

// round 6
// speedup vs baseline: 1.5411x; 1.5411x over previous
#include <cuda_runtime.h>
#include <math.h>

// ---- problem constants -----------------------------------------------------
constexpr int NN   = 62;    // nodes per graph
constexpr int NP   = 64;    // padded nodes
constexpr int BB   = 512;   // graphs
constexpr int FIN  = 128;   // input features
constexpr int HH   = 64;    // hidden
constexpr int CC   = 3;     // classes

// smem row strides (floats) — all chosen 16B-aligned and bank-conflict-free
constexpr int XS  = 132;    // X rows: 528B; 4-row lane groups land 64B apart mod 128
constexpr int WS  = 68;     // W1T rows: 272B; 16 contiguous float4 -> 2 wavefronts
constexpr int A2S = 68;     // A2 rows: 272B; 4-row groups 64B apart mod 128
constexpr int MS  = 68;     // M rows: 272B

constexpr int SZ_X    = NP * XS;      // 8448
constexpr int SZ_W1T  = FIN * WS;     // 8704
constexpr int SZ_A2   = NP * A2S;     // 4352
constexpr int SZ_M    = NP * MS;      // 4352
constexpr int SZ_B1   = HH;           // 64
constexpr int SZ_POOL = 16 * HH;      // 1024
constexpr int SZ_PD   = HH;           // 64
constexpr int SMEM_FLOATS = SZ_X + SZ_W1T + SZ_A2 + SZ_M + SZ_B1 + SZ_POOL + SZ_PD;

__device__ float g_A2[NP * NP];     // padded 64x64, rows/cols >=62 are zero
__device__ float g_W1T[FIN * HH];   // W1 transposed: [k][h]

// ---- prep: 64 blocks x 64 threads. Block b computes A2 row b and transposes
// one W1 row. Uses A2 = D (A D^2 A) D  so A is never normalized in place. ----
__global__ void prep_kernel(const float* __restrict__ tril,
                            const float* __restrict__ W1) {
    __shared__ float A[NP][NP];   // zero-padded
    __shared__ float dv[NP];      // dinv
    __shared__ float d2[NP];      // dinv^2
    __shared__ float trow[NP];    // A[b][k] * d2[k]
    const int j = threadIdx.x;    // 0..63
    const int b = blockIdx.x;     // 0..63

    for (int idx = j; idx < NP * NP; idx += 64) {
        int i = idx >> 6, jj = idx & 63;
        float v = 0.f;
        if (i < NN && jj < NN) {
            int a_ = i > jj ? i : jj;
            int b_ = i > jj ? jj : i;
            v = tril[a_ * (a_ + 1) / 2 + b_];
        }
        A[i][jj] = v;
    }
    __syncthreads();

    {
        float s = 0.f;
        #pragma unroll 4
        for (int k = 0; k < NP; ++k) s += fabsf(A[j][k]);
        float di = s > 0.f ? rsqrtf(s) : 0.f;
        dv[j] = di;
        d2[j] = di * di;
    }
    __syncthreads();

    trow[j] = A[b][j] * d2[j];
    __syncthreads();

    {
        float s = 0.f;
        #pragma unroll 4
        for (int k = 0; k < NP; ++k) s += trow[k] * A[k][j];  // col read: conflict-free
        g_A2[b * NP + j] = dv[b] * s * dv[j];
    }

    // W1 transpose: g_W1T[k][h] = W1[h][k]
    for (int k = j; k < FIN; k += 64)
        g_W1T[k * HH + b] = W1[b * FIN + k];
}

// ---- main: 512 CTAs x 256 threads; 4x4 register-tiled GEMMs ----------------
__global__ __launch_bounds__(256, 2)
void graph_kernel(const float* __restrict__ x,
                  const float* __restrict__ b1,
                  const float* __restrict__ W2,
                  const float* __restrict__ b2,
                  float* __restrict__ out) {
    extern __shared__ float sm[];
    float* sX      = sm;                      // SZ_X
    float* sW1T    = sX    + SZ_X;            // SZ_W1T
    float* sA2     = sW1T  + SZ_W1T;          // SZ_A2
    float* sM      = sA2   + SZ_A2;           // SZ_M
    float* sB1     = sM    + SZ_M;            // 64
    float* sPool   = sB1   + SZ_B1;           // 16*64
    float* sPooled = sPool + SZ_POOL;         // 64

    const int tid = threadIdx.x;
    const int g   = blockIdx.x;
    const int tc  = tid & 15;      // col group: cols c0..c0+3
    const int tr  = tid >> 4;      // row group: rows r0..r0+3
    const int c0  = tc * 4;
    const int r0  = tr * 4;

    // ---- stage 0: stage X (zero-padded), W1T, A2, b1 ----
    const float4* xg = (const float4*)(x + (size_t)g * NN * FIN);
    for (int t = tid; t < NN * (FIN / 4); t += 256) {
        int i  = t >> 5;           // FIN/4 == 32
        int f4 = t & 31;
        *(float4*)(sX + i * XS + f4 * 4) = xg[t];
    }
    for (int t = tid; t < 2 * XS; t += 256)      // zero rows 62,63
        sX[NN * XS + t] = 0.f;

    const float4* w1t4 = (const float4*)g_W1T;
    for (int t = tid; t < FIN * (HH / 4); t += 256) {
        int k  = t >> 4;           // HH/4 == 16
        int c4 = t & 15;
        *(float4*)(sW1T + k * WS + c4 * 4) = w1t4[t];
    }
    const float4* a24 = (const float4*)g_A2;
    for (int t = tid; t < NP * (NP / 4); t += 256) {
        int i  = t >> 4;
        int j4 = t & 15;
        *(float4*)(sA2 + i * A2S + j4 * 4) = a24[t];
    }
    if (tid < HH) sB1[tid] = b1[tid];
    __syncthreads();

    // ---- stage 1: M = X @ W1T   (4x4 register tile per thread) ----
    {
        float acc[4][4];
        #pragma unroll
        for (int r = 0; r < 4; ++r)
            #pragma unroll
            for (int c = 0; c < 4; ++c) acc[r][c] = 0.f;

        #pragma unroll 2
        for (int k4 = 0; k4 < FIN / 4; ++k4) {
            float xr[4][4];
            #pragma unroll
            for (int r = 0; r < 4; ++r) {
                float4 v = *(const float4*)(sX + (r0 + r) * XS + k4 * 4);
                xr[r][0] = v.x; xr[r][1] = v.y; xr[r][2] = v.z; xr[r][3] = v.w;
            }
            #pragma unroll
            for (int kk = 0; kk < 4; ++kk) {
                float4 wv = *(const float4*)(sW1T + (k4 * 4 + kk) * WS + c0);
                #pragma unroll
                for (int r = 0; r < 4; ++r) {
                    acc[r][0] += xr[r][kk] * wv.x;
                    acc[r][1] += xr[r][kk] * wv.y;
                    acc[r][2] += xr[r][kk] * wv.z;
                    acc[r][3] += xr[r][kk] * wv.w;
                }
            }
        }
        #pragma unroll
        for (int r = 0; r < 4; ++r)
            *(float4*)(sM + (r0 + r) * MS + c0) =
                make_float4(acc[r][0], acc[r][1], acc[r][2], acc[r][3]);
    }
    __syncthreads();

    // ---- stage 2: Y = A2 @ M ; relu(Y+b1); partial pool over this thread's rows ----
    {
        float acc[4][4];
        #pragma unroll
        for (int r = 0; r < 4; ++r)
            #pragma unroll
            for (int c = 0; c < 4; ++c) acc[r][c] = 0.f;

        #pragma unroll 2
        for (int k4 = 0; k4 < NP / 4; ++k4) {
            float ar[4][4];
            #pragma unroll
            for (int r = 0; r < 4; ++r) {
                float4 v = *(const float4*)(sA2 + (r0 + r) * A2S + k4 * 4);
                ar[r][0] = v.x; ar[r][1] = v.y; ar[r][2] = v.z; ar[r][3] = v.w;
            }
            #pragma unroll
            for (int kk = 0; kk < 4; ++kk) {
                float4 mv = *(const float4*)(sM + (k4 * 4 + kk) * MS + c0);
                #pragma unroll
                for (int r = 0; r < 4; ++r) {
                    acc[r][0] += ar[r][kk] * mv.x;
                    acc[r][1] += ar[r][kk] * mv.y;
                    acc[r][2] += ar[r][kk] * mv.z;
                    acc[r][3] += ar[r][kk] * mv.w;
                }
            }
        }

        float4 bb = *(const float4*)(sB1 + c0);
        float part[4] = {0.f, 0.f, 0.f, 0.f};
        #pragma unroll
        for (int r = 0; r < 4; ++r) {
            if (r0 + r < NN) {   // rows 62,63 are padding: Y=0 but relu(b1)!=0 -> mask
                part[0] += fmaxf(acc[r][0] + bb.x, 0.f);
                part[1] += fmaxf(acc[r][1] + bb.y, 0.f);
                part[2] += fmaxf(acc[r][2] + bb.z, 0.f);
                part[3] += fmaxf(acc[r][3] + bb.w, 0.f);
            }
        }
        *(float4*)(sPool + tr * HH + c0) =
            make_float4(part[0], part[1], part[2], part[3]);
    }
    __syncthreads();

    // ---- stage 3: reduce pool over 16 row-groups -> latent; tiny head ----
    if (tid < HH) {
        float p = 0.f;
        #pragma unroll
        for (int t = 0; t < 16; ++t) p += sPool[t * HH + tid];
        sPooled[tid] = p;
        out[(size_t)g * HH + tid] = p;          // latent_v
    }
    __syncthreads();

    if (tid < 32) {
        float p0 = sPooled[tid], p1 = sPooled[tid + 32];
        float l[CC];
        #pragma unroll
        for (int cc = 0; cc < CC; ++cc) {
            l[cc] = p0 * W2[cc * HH + tid] + p1 * W2[cc * HH + tid + 32];
            #pragma unroll
            for (int off = 16; off; off >>= 1)
                l[cc] += __shfl_xor_sync(0xffffffffu, l[cc], off);
        }
        if (tid == 0) {
            float l0 = l[0] + b2[0];
            float l1 = l[1] + b2[1];
            float l2 = l[2] + b2[2];
            float m  = fmaxf(l0, fmaxf(l1, l2));
            float lse = m + logf(expf(l0 - m) + expf(l1 - m) + expf(l2 - m));
            float* lp = out + (size_t)BB * HH + (size_t)g * CC;
            lp[0] = l0 - lse;
            lp[1] = l1 - lse;
            lp[2] = l2 - lse;
        }
    }
}

// ---- launch -----------------------------------------------------------------
extern "C" void kernel_launch(void* const* d_in, const int* in_sizes, int n_in,
                              void* d_out, int out_size) {
    (void)in_sizes; (void)n_in; (void)out_size;
    const float* x    = (const float*)d_in[0];
    const float* tril = (const float*)d_in[1];
    const float* W1   = (const float*)d_in[2];
    const float* b1   = (const float*)d_in[3];
    const float* W2   = (const float*)d_in[4];
    const float* b2   = (const float*)d_in[5];
    float* out = (float*)d_out;

    const int smem_bytes = SMEM_FLOATS * (int)sizeof(float);
    cudaFuncSetAttribute(graph_kernel,
                         cudaFuncAttributeMaxDynamicSharedMemorySize, smem_bytes);

    prep_kernel<<<64, 64>>>(tril, W1);
    graph_kernel<<<BB, 256, smem_bytes>>>(x, b1, W2, b2, out);
}